// round 4
// baseline (speedup 1.0000x reference)
#include <cuda_runtime.h>

#define BATCH 2048
#define TLEN  512
#define KLAB  24
#define FULLMASK 0xffffffffu

// Scratch (no allocations allowed).
__device__ float g_Mexp[KLAB * KLAB];
__device__ float g_scratch[BATCH];
__device__ int   g_tags64;   // 1 if tags buffer is int64, 0 if int32

// ---------------------------------------------------------------------------
// Kernel 1: M[j,i] = exp(trans[j,i])  (exp(-10000) underflows to exact 0 ==
// the reference's forbidden-transition mask), plus tags-dtype probe:
// if tags are int64 (LE, values 0..21) every odd 32-bit word is exactly 0.
// ---------------------------------------------------------------------------
__global__ void prep_kernel(const float* __restrict__ trans,
                            const unsigned int* __restrict__ tags_raw) {
    __shared__ unsigned int s_or[256];
    const int tid = threadIdx.x;

    // Grid-stride over all 576 entries (256 threads < 576).
    for (int i = tid; i < KLAB * KLAB; i += 256)
        g_Mexp[i] = expf(trans[i]);

    // Probe 1024 odd words (first 2048 words valid in BOTH interpretations).
    unsigned int v = 0;
    for (int i = tid; i < 1024; i += 256)
        v |= tags_raw[2 * i + 1];
    s_or[tid] = v;
    __syncthreads();
    for (int o = 128; o > 0; o >>= 1) {
        if (tid < o) s_or[tid] |= s_or[tid + o];
        __syncthreads();
    }
    if (tid == 0) g_tags64 = (s_or[0] == 0u) ? 1 : 0;
}

// ---------------------------------------------------------------------------
// Kernel 2: one warp per batch chain.
// Lane j owns alpha[j] and row j of M (24 registers).
// alpha'[j] = log( sum_i M[j,i] * exp(alpha[i]-m) ) + m + feat[t,j]
// ---------------------------------------------------------------------------
__global__ __launch_bounds__(128, 8)
void crf_forward_kernel(const float* __restrict__ feats,
                        const float* __restrict__ trans,
                        const void* __restrict__ tags_any,
                        const int* __restrict__ start_ptr) {
    const int warp = threadIdx.x >> 5;
    const int lane = threadIdx.x & 31;
    const int b = blockIdx.x * 4 + warp;

    const int start = start_ptr ? *start_ptr : 22;  // int32 low word OK for int64 LE

    // Row of M for this lane (lanes >= K read row 0; their alpha is masked).
    float Mrow[KLAB];
    {
        const int r = (lane < KLAB) ? lane : 0;
        #pragma unroll
        for (int i = 0; i < KLAB; i++) Mrow[i] = g_Mexp[r * KLAB + i];
    }

    const float* fb = feats + (size_t)b * TLEN * KLAB;

    float alpha;
    if (lane < KLAB) alpha = (lane == start) ? 0.0f : -10000.0f;
    else             alpha = -1e30f;

    float feat_next = (lane < KLAB) ? fb[(size_t)1 * KLAB + lane] : 0.0f;

    for (int t = 1; t < TLEN; t++) {
        // warp max over alpha
        float m = alpha;
        #pragma unroll
        for (int o = 16; o > 0; o >>= 1)
            m = fmaxf(m, __shfl_xor_sync(FULLMASK, m, o));

        float p = __expf(alpha - m);   // masked lanes -> 0

        float feat = feat_next;
        if (t + 1 < TLEN)
            feat_next = (lane < KLAB) ? fb[(size_t)(t + 1) * KLAB + lane] : 0.0f;

        // dot = sum_i Mrow[i] * p_i  (4 split accumulators)
        float a0 = 0.f, a1 = 0.f, a2 = 0.f, a3 = 0.f;
        #pragma unroll
        for (int i = 0; i < KLAB; i += 4) {
            a0 = fmaf(Mrow[i + 0], __shfl_sync(FULLMASK, p, i + 0), a0);
            a1 = fmaf(Mrow[i + 1], __shfl_sync(FULLMASK, p, i + 1), a1);
            a2 = fmaf(Mrow[i + 2], __shfl_sync(FULLMASK, p, i + 2), a2);
            a3 = fmaf(Mrow[i + 3], __shfl_sync(FULLMASK, p, i + 3), a3);
        }
        float dot = (a0 + a1) + (a2 + a3);

        alpha = (lane < KLAB) ? (__logf(dot) + m + feat) : -1e30f;
    }

    // forward_score = logsumexp over lanes
    float m = alpha;
    #pragma unroll
    for (int o = 16; o > 0; o >>= 1)
        m = fmaxf(m, __shfl_xor_sync(FULLMASK, m, o));
    float e = __expf(alpha - m);
    #pragma unroll
    for (int o = 16; o > 0; o >>= 1)
        e += __shfl_xor_sync(FULLMASK, e, o);
    const float forward = m + __logf(e);

    // gold score, lane-strided over T; dtype-dispatched tag reads
    float g = 0.0f;
    if (g_tags64) {
        const long long* tb = (const long long*)tags_any + (size_t)b * TLEN;
        for (int t = 1 + lane; t < TLEN; t += 32) {
            const int tc = (int)tb[t];
            const int tp = (int)tb[t - 1];
            g += trans[tc * KLAB + tp] + fb[(size_t)t * KLAB + tc];
        }
    } else {
        const int* tb = (const int*)tags_any + (size_t)b * TLEN;
        for (int t = 1 + lane; t < TLEN; t += 32) {
            const int tc = tb[t];
            const int tp = tb[t - 1];
            g += trans[tc * KLAB + tp] + fb[(size_t)t * KLAB + tc];
        }
    }
    #pragma unroll
    for (int o = 16; o > 0; o >>= 1)
        g += __shfl_xor_sync(FULLMASK, g, o);

    if (lane == 0) g_scratch[b] = forward - g;
}

// ---------------------------------------------------------------------------
// Kernel 3: deterministic fixed-order mean reduction.
// ---------------------------------------------------------------------------
__global__ void reduce_kernel(float* __restrict__ out) {
    __shared__ float s[256];
    float v = 0.0f;
    for (int i = threadIdx.x; i < BATCH; i += 256) v += g_scratch[i];
    s[threadIdx.x] = v;
    __syncthreads();
    for (int o = 128; o > 0; o >>= 1) {
        if (threadIdx.x < o) s[threadIdx.x] += s[threadIdx.x + o];
        __syncthreads();
    }
    if (threadIdx.x == 0) out[0] = s[0] / (float)BATCH;
}

// ---------------------------------------------------------------------------
extern "C" void kernel_launch(void* const* d_in, const int* in_sizes, int n_in,
                              void* d_out, int out_size) {
    const float* feats = (const float*)d_in[0];
    const float* trans = (const float*)d_in[1];
    const void*  tags  = d_in[2];
    const int*   start = (n_in > 3) ? (const int*)d_in[3] : nullptr;
    float* out = (float*)d_out;

    prep_kernel<<<1, 256>>>(trans, (const unsigned int*)tags);
    crf_forward_kernel<<<BATCH / 4, 128>>>(feats, trans, tags, start);
    reduce_kernel<<<1, 256>>>(out);
}

// round 6
// speedup vs baseline: 1.2912x; 1.2912x over previous
#include <cuda_runtime.h>

#define BATCH 2048
#define TLEN  512
#define KLAB  24
#define FULLMASK 0xffffffffu

__device__ float g_scratch[BATCH];

// ---------------------------------------------------------------------------
// Forward kernel: one warp per batch chain, 2 warps (64 thr) per block.
// Lane j owns alpha[j] and row j of M = exp(trans) (24 registers).
// alpha'[j] = log( sum_i M[j,i] * exp(alpha[i]-m) ) + m + feat[t,j],
// with m = alpha[0] (lane-0 pivot; provably finite, bounded spread).
// exp(trans) computed per-block in smem (replaces the prep kernel).
// ---------------------------------------------------------------------------
__global__ __launch_bounds__(64, 8)
void crf_forward_kernel(const float* __restrict__ feats,
                        const float* __restrict__ trans,
                        const void* __restrict__ tags_any,
                        const int* __restrict__ start_ptr) {
    __shared__ float sM[KLAB * KLAB];

    const int warp = threadIdx.x >> 5;
    const int lane = threadIdx.x & 31;
    const int b = blockIdx.x * 2 + warp;

    const int start = start_ptr ? *start_ptr : 22;  // int32 low word OK either way

    // Per-block exp(trans): exp(-10000) underflows to exact 0 == the
    // reference's forbidden-transition mask.
    for (int i = threadIdx.x; i < KLAB * KLAB; i += 64)
        sM[i] = __expf(trans[i]);

    // tags dtype probe (once per warp, 1 redux instr): if int64 (LE, values
    // 0..21), odd 32-bit words are all zero. Probe stays inside the first
    // 8KB, valid under BOTH interpretations.
    const unsigned int* traw = (const unsigned int*)tags_any + (b & 31) * 64;
    const unsigned int oddw = traw[2 * lane + 1];
    const int tags64 = (__reduce_or_sync(FULLMASK, oddw) == 0u) ? 1 : 0;

    __syncthreads();

    // Row of M for this lane (lanes >= K read row 0; their alpha is masked).
    float Mrow[KLAB];
    {
        const int r = (lane < KLAB) ? lane : 0;
        #pragma unroll
        for (int i = 0; i < KLAB; i++) Mrow[i] = sM[r * KLAB + i];
    }

    const float* fb = feats + (size_t)b * TLEN * KLAB;

    // Analytic first step: alpha_1[j] = trans[j, start] + feat[1, j]
    // (all other logsumexp terms are exp(-~10000) == 0 in fp32, exactly as
    // in the reference's shifted computation).
    float alpha;
    if (lane < KLAB)
        alpha = trans[lane * KLAB + start] + fb[(size_t)1 * KLAB + lane];
    else
        alpha = -1e30f;

    // Prefetch ring, distance 4: fbuf[t & 3] holds feat[t].
    float fbuf[4];
    #pragma unroll
    for (int t = 2; t < 6; t++)
        fbuf[t & 3] = (lane < KLAB) ? fb[(size_t)t * KLAB + lane] : 0.0f;

    #pragma unroll 4
    for (int t = 2; t < TLEN; t++) {
        const float feat = fbuf[t & 3];
        // Refill the slot we just consumed with feat[t+4].
        if (t + 4 < TLEN)
            fbuf[t & 3] = (lane < KLAB) ? fb[(size_t)(t + 4) * KLAB + lane] : 0.0f;

        // Pivot shift: lane 0's alpha (finite; spread across lanes bounded).
        const float m = __shfl_sync(FULLMASK, alpha, 0);
        const float p = __expf(alpha - m);   // masked / -10000 lanes -> 0

        // dot = sum_i Mrow[i] * p_i  (4 split accumulators)
        float a0 = 0.f, a1 = 0.f, a2 = 0.f, a3 = 0.f;
        #pragma unroll
        for (int i = 0; i < KLAB; i += 4) {
            a0 = fmaf(Mrow[i + 0], __shfl_sync(FULLMASK, p, i + 0), a0);
            a1 = fmaf(Mrow[i + 1], __shfl_sync(FULLMASK, p, i + 1), a1);
            a2 = fmaf(Mrow[i + 2], __shfl_sync(FULLMASK, p, i + 2), a2);
            a3 = fmaf(Mrow[i + 3], __shfl_sync(FULLMASK, p, i + 3), a3);
        }
        const float dot = (a0 + a1) + (a2 + a3);

        // __logf(0) = -inf for the start row: propagates as p=0, matching
        // the reference's ~-10000 track (both vanish in every exp).
        alpha = (lane < KLAB) ? (__logf(dot) + m + feat) : -1e30f;
    }

    // forward_score = logsumexp over lanes
    float mx = alpha;
    #pragma unroll
    for (int o = 16; o > 0; o >>= 1)
        mx = fmaxf(mx, __shfl_xor_sync(FULLMASK, mx, o));
    float e = __expf(alpha - mx);
    #pragma unroll
    for (int o = 16; o > 0; o >>= 1)
        e += __shfl_xor_sync(FULLMASK, e, o);
    const float forward = mx + __logf(e);

    // gold score, lane-strided over T; dtype-dispatched tag reads
    float g = 0.0f;
    if (tags64) {
        const long long* tb = (const long long*)tags_any + (size_t)b * TLEN;
        for (int t = 1 + lane; t < TLEN; t += 32) {
            const int tc = (int)tb[t];
            const int tp = (int)tb[t - 1];
            g += trans[tc * KLAB + tp] + fb[(size_t)t * KLAB + tc];
        }
    } else {
        const int* tb = (const int*)tags_any + (size_t)b * TLEN;
        for (int t = 1 + lane; t < TLEN; t += 32) {
            const int tc = tb[t];
            const int tp = tb[t - 1];
            g += trans[tc * KLAB + tp] + fb[(size_t)t * KLAB + tc];
        }
    }
    #pragma unroll
    for (int o = 16; o > 0; o >>= 1)
        g += __shfl_xor_sync(FULLMASK, g, o);

    if (lane == 0) g_scratch[b] = forward - g;
}

// ---------------------------------------------------------------------------
// Deterministic fixed-order mean reduction.
// ---------------------------------------------------------------------------
__global__ void reduce_kernel(float* __restrict__ out) {
    __shared__ float s[256];
    float v = 0.0f;
    for (int i = threadIdx.x; i < BATCH; i += 256) v += g_scratch[i];
    s[threadIdx.x] = v;
    __syncthreads();
    for (int o = 128; o > 0; o >>= 1) {
        if (threadIdx.x < o) s[threadIdx.x] += s[threadIdx.x + o];
        __syncthreads();
    }
    if (threadIdx.x == 0) out[0] = s[0] / (float)BATCH;
}

// ---------------------------------------------------------------------------
extern "C" void kernel_launch(void* const* d_in, const int* in_sizes, int n_in,
                              void* d_out, int out_size) {
    const float* feats = (const float*)d_in[0];
    const float* trans = (const float*)d_in[1];
    const void*  tags  = d_in[2];
    const int*   start = (n_in > 3) ? (const int*)d_in[3] : nullptr;
    float* out = (float*)d_out;

    crf_forward_kernel<<<BATCH / 2, 64>>>(feats, trans, tags, start);
    reduce_kernel<<<1, 256>>>(out);
}

// round 9
// speedup vs baseline: 1.9710x; 1.5265x over previous
#include <cuda_runtime.h>

#define BATCH 2048
#define TLEN  512
#define KLAB  24
#define FULLMASK 0xffffffffu

__device__ float g_scratch[BATCH];

// ---------------------------------------------------------------------------
// Forward kernel: 4 chains per warp, 8 lanes per chain, 3 labels per lane.
// lane = 8*c + g; chain b = blockIdx.x*4 + c; lane owns labels 3g..3g+2.
// Prob-domain recurrence:  A'[j] = exp(feat[t,j]) * sum_i M[j,i] * A[i],
// M = exp(trans) (rows in registers), with exact 2^k rescaling every 4 steps.
// forward = log(sum_j A[j]) + esum*ln2.
// ---------------------------------------------------------------------------
__global__ __launch_bounds__(32)
void crf_forward_kernel(const float* __restrict__ feats,
                        const float* __restrict__ trans,
                        const void* __restrict__ tags_any,
                        const int* __restrict__ start_ptr) {
    const int lane = threadIdx.x;
    const int g = lane & 7;        // label group: owns labels 3g..3g+2
    const int c = lane >> 3;       // chain slot within warp
    const int b = blockIdx.x * 4 + c;
    const int gsel = lane & 0x18;  // 8*c : base lane of my chain group

    const int start = start_ptr ? *start_ptr : 22;

    // tags dtype probe (int64 LE with values 0..21 -> odd words all zero).
    // Reads < 8KB into a >=4MB buffer: safe under both interpretations.
    const unsigned int* traw = (const unsigned int*)tags_any + (blockIdx.x & 31) * 64;
    const int tags64 = (__reduce_or_sync(FULLMASK, traw[2 * lane + 1]) == 0u) ? 1 : 0;

    // M rows for this lane: M[r][i] = exp(trans[(3g+r)*K + i]).
    // exp(-10000) underflows to exact 0 == the reference's masking.
    float M[3][KLAB];
    #pragma unroll
    for (int r = 0; r < 3; r++)
        #pragma unroll
        for (int i = 0; i < KLAB; i++)
            M[r][i] = __expf(trans[(3 * g + r) * KLAB + i]);

    const float* fbase = feats + (size_t)b * TLEN * KLAB;      // chain base
    const float* fb    = fbase + 3 * g;                        // our 3 labels

    // Analytic step 1: alpha1[j] = trans[j,start] + feat[1,j]; A = exp(alpha1).
    float A[3];
    #pragma unroll
    for (int r = 0; r < 3; r++)
        A[r] = __expf(trans[(3 * g + r) * KLAB + start] + fb[1 * KLAB + r]);

    int esum = 0;  // accumulated power-of-2 scale (same value in all 8 lanes)

    // feats prefetch ring, distance 4.
    float ring[4][3];
    #pragma unroll
    for (int t = 2; t < 6; t++)
        #pragma unroll
        for (int r = 0; r < 3; r++)
            ring[t & 3][r] = fb[(size_t)t * KLAB + r];

    #pragma unroll 4
    for (int t = 2; t < TLEN; t++) {
        float feat0 = ring[t & 3][0], feat1 = ring[t & 3][1], feat2 = ring[t & 3][2];
        if (t + 4 < TLEN) {
            ring[t & 3][0] = fb[(size_t)(t + 4) * KLAB + 0];
            ring[t & 3][1] = fb[(size_t)(t + 4) * KLAB + 1];
            ring[t & 3][2] = fb[(size_t)(t + 4) * KLAB + 2];
        }
        const float E0 = __expf(feat0), E1 = __expf(feat1), E2 = __expf(feat2);

        // Gather all 24 A values of my chain (3 per source lane) and
        // accumulate the 3 dots. One shfl serves all 4 chains in the warp.
        float p0[3] = {0.f, 0.f, 0.f}, p1[3] = {0.f, 0.f, 0.f};
        #pragma unroll
        for (int s = 0; s < 8; s++) {
            const int src = gsel + s;
            const float a0 = __shfl_sync(FULLMASK, A[0], src);
            const float a1 = __shfl_sync(FULLMASK, A[1], src);
            const float a2 = __shfl_sync(FULLMASK, A[2], src);
            const int i = 3 * s;
            #pragma unroll
            for (int r = 0; r < 3; r++) {
                p0[r] = fmaf(M[r][i + 0], a0, p0[r]);
                p1[r] = fmaf(M[r][i + 1], a1, p1[r]);
                p0[r] = fmaf(M[r][i + 2], a2, p0[r]);
            }
        }
        A[0] = E0 * (p0[0] + p1[0]);
        A[1] = E1 * (p0[1] + p1[1]);
        A[2] = E2 * (p0[2] + p1[2]);

        // Exact 2^k rescale every 4 steps (max-norm over the chain group).
        if ((t & 3) == 0) {
            float mx = fmaxf(fmaxf(A[0], A[1]), A[2]);
            mx = fmaxf(mx, __shfl_xor_sync(FULLMASK, mx, 1));
            mx = fmaxf(mx, __shfl_xor_sync(FULLMASK, mx, 2));
            mx = fmaxf(mx, __shfl_xor_sync(FULLMASK, mx, 4));
            const int e = (int)((__float_as_uint(mx) >> 23) & 0xFF) - 127;
            const float scale = __uint_as_float((unsigned int)(127 - e) << 23); // 2^-e
            esum += e;
            A[0] *= scale; A[1] *= scale; A[2] *= scale;
        }
    }

    // forward = log(sum_j A[j]) + esum * ln2
    float s3 = (A[0] + A[1]) + A[2];
    s3 += __shfl_xor_sync(FULLMASK, s3, 1);
    s3 += __shfl_xor_sync(FULLMASK, s3, 2);
    s3 += __shfl_xor_sync(FULLMASK, s3, 4);
    const float forward = __logf(s3) + (float)((double)esum * 0.6931471805599453);

    // gold score: 8 lanes per chain, stride-8 over t; dtype-dispatched tags.
    float gg = 0.0f;
    if (tags64) {
        const long long* tb = (const long long*)tags_any + (size_t)b * TLEN;
        for (int t = 1 + g; t < TLEN; t += 8) {
            const int tc = (int)tb[t];
            const int tp = (int)tb[t - 1];
            gg += trans[tc * KLAB + tp] + fbase[(size_t)t * KLAB + tc];
        }
    } else {
        const int* tb = (const int*)tags_any + (size_t)b * TLEN;
        for (int t = 1 + g; t < TLEN; t += 8) {
            const int tc = tb[t];
            const int tp = tb[t - 1];
            gg += trans[tc * KLAB + tp] + fbase[(size_t)t * KLAB + tc];
        }
    }
    gg += __shfl_xor_sync(FULLMASK, gg, 1);
    gg += __shfl_xor_sync(FULLMASK, gg, 2);
    gg += __shfl_xor_sync(FULLMASK, gg, 4);

    if (g == 0) g_scratch[b] = forward - gg;
}

// ---------------------------------------------------------------------------
// Deterministic fixed-order mean reduction.
// ---------------------------------------------------------------------------
__global__ void reduce_kernel(float* __restrict__ out) {
    __shared__ float s[256];
    float v = 0.0f;
    for (int i = threadIdx.x; i < BATCH; i += 256) v += g_scratch[i];
    s[threadIdx.x] = v;
    __syncthreads();
    for (int o = 128; o > 0; o >>= 1) {
        if (threadIdx.x < o) s[threadIdx.x] += s[threadIdx.x + o];
        __syncthreads();
    }
    if (threadIdx.x == 0) out[0] = s[0] / (float)BATCH;
}

// ---------------------------------------------------------------------------
extern "C" void kernel_launch(void* const* d_in, const int* in_sizes, int n_in,
                              void* d_out, int out_size) {
    const float* feats = (const float*)d_in[0];
    const float* trans = (const float*)d_in[1];
    const void*  tags  = d_in[2];
    const int*   start = (n_in > 3) ? (const int*)d_in[3] : nullptr;
    float* out = (float*)d_out;

    crf_forward_kernel<<<BATCH / 4, 32>>>(feats, trans, tags, start);
    reduce_kernel<<<1, 256>>>(out);
}